// round 10
// baseline (speedup 1.0000x reference)
#include <cuda_runtime.h>

#define B_ 32
#define T_ 4096
#define D_ 64
#define S_ 64
#define H_ 128
#define EPSV 1e-10f

// g_e padded by 512 floats on each side so prefetch rings load unconditionally.
__device__ __align__(16) float g_e_raw[B_ * T_ * S_ + 1024];
__device__ __align__(16) float g_alpha[B_ * T_ * S_];
__device__ __align__(16) float g_beta[B_ * T_ * S_];
__device__ __align__(16) float g_M[S_ * S_];
__device__ __align__(16) float g_pi[S_];
__device__ __align__(16) float g_margpart[B_ * 16 * S_];

typedef unsigned long long u64;

__device__ __forceinline__ u64 pack2(float x, float y) {
    u64 r; asm("mov.b64 %0, {%1, %2};" : "=l"(r) : "f"(x), "f"(y)); return r;
}
__device__ __forceinline__ void unpack2(u64 v, float& x, float& y) {
    asm("mov.b64 {%0, %1}, %2;" : "=f"(x), "=f"(y) : "l"(v));
}
__device__ __forceinline__ u64 fma2(u64 a, u64 b, u64 c) {
    u64 d; asm("fma.rn.f32x2 %0, %1, %2, %3;" : "=l"(d) : "l"(a), "l"(b), "l"(c)); return d;
}
__device__ __forceinline__ u64 add2(u64 a, u64 b) {
    u64 d; asm("add.rn.f32x2 %0, %1, %2;" : "=l"(d) : "l"(a), "l"(b)); return d;
}

// ---------------- setup ----------------
__global__ void setup_kernel(const float* __restrict__ ltm, const float* __restrict__ lip,
                             const float* __restrict__ lr, const float* __restrict__ lp,
                             float* __restrict__ out_dur) {
    int j = threadIdx.x;
    float row[S_];
    float m = -1e30f;
#pragma unroll
    for (int k = 0; k < S_; k++) {
        float v = (k == j) ? -1e10f : ltm[j * S_ + k];
        row[k] = v;
        m = fmaxf(m, v);
    }
    float s = 0.f;
#pragma unroll
    for (int k = 0; k < S_; k++) { row[k] = expf(row[k] - m); s += row[k]; }
    float inv = 1.f / s;
#pragma unroll
    for (int k = 0; k < S_; k++) g_M[j * S_ + k] = row[k] * inv + EPSV;

    float m2 = -1e30f;
#pragma unroll
    for (int k = 0; k < S_; k++) m2 = fmaxf(m2, lip[k]);
    float s2 = 0.f;
#pragma unroll
    for (int k = 0; k < S_; k++) s2 += expf(lip[k] - m2);
    g_pi[j] = expf(lip[j] - m2) / s2;

    float r = expf(lr[j]);
    float p = 1.f / (1.f + expf(-lp[j]));
    out_dur[j] = r * (1.f - p) / p;
}

// ---------------- emission MLP + softmax (unchanged, passing) ----------------
__global__ void __launch_bounds__(128) mlp_kernel(
    const float* __restrict__ obs,
    const float* __restrict__ W1, const float* __restrict__ b1,
    const float* __restrict__ W2, const float* __restrict__ b2,
    const float* __restrict__ W3, const float* __restrict__ b3) {
    extern __shared__ float sm[];
    float* W1s = sm;
    float* W2s = W1s + D_ * H_;
    float* W3s = W2s + H_ * H_;
    float* b1s = W3s + H_ * S_;
    float* b2s = b1s + H_;
    float* b3s = b2s + H_;
    float* bufs = b3s + S_;

    int tid = threadIdx.x;
    for (int i = tid; i < (D_ * H_) / 4; i += 128)
        ((float4*)W1s)[i] = ((const float4*)W1)[i];
    for (int i = tid; i < (H_ * H_) / 4; i += 128)
        ((float4*)W2s)[i] = ((const float4*)W2)[i];
    for (int i = tid; i < (H_ * S_) / 4; i += 128)
        ((float4*)W3s)[i] = ((const float4*)W3)[i];
    if (tid < H_) { b1s[tid] = b1[tid]; b2s[tid] = b2[tid]; }
    if (tid < S_) b3s[tid] = b3[tid];
    __syncthreads();

    int w = tid >> 5, l = tid & 31;
    float* bufA = bufs + w * 4096;
    float* bufB = bufA + 2048;
    const unsigned FULL = 0xffffffffu;
    float* ge = g_e_raw + 512;

    int rowbase = blockIdx.x * 128 + w * 32;

    for (int g = 0; g < 4; g++) {
        int r0 = rowbase + g * 8;
        __syncwarp();
#pragma unroll
        for (int rr = 0; rr < 8; rr++) {
            float2 xv = *(const float2*)&obs[(size_t)(r0 + rr) * D_ + 2 * l];
            *(float4*)&bufA[rr * 128 + 4 * l] = make_float4(xv.x, xv.x, xv.y, xv.y);
        }
        __syncwarp();

        u64 acc[8][2];
        {
            u64 bias0 = *(const u64*)&b1s[4 * l];
            u64 bias1 = *(const u64*)&b1s[4 * l + 2];
#pragma unroll
            for (int rr = 0; rr < 8; rr++) { acc[rr][0] = bias0; acc[rr][1] = bias1; }
        }
#pragma unroll 4
        for (int kp = 0; kp < 32; kp++) {
            ulonglong2 w0 = *(const ulonglong2*)&W1s[(2 * kp) * H_ + 4 * l];
            ulonglong2 w1 = *(const ulonglong2*)&W1s[(2 * kp + 1) * H_ + 4 * l];
#pragma unroll
            for (int rr = 0; rr < 8; rr++) {
                ulonglong2 xq = *(const ulonglong2*)&bufA[rr * 128 + 4 * kp];
                acc[rr][0] = fma2(xq.x, w0.x, acc[rr][0]);
                acc[rr][1] = fma2(xq.x, w0.y, acc[rr][1]);
                acc[rr][0] = fma2(xq.y, w1.x, acc[rr][0]);
                acc[rr][1] = fma2(xq.y, w1.y, acc[rr][1]);
            }
        }
#pragma unroll
        for (int rr = 0; rr < 8; rr++) {
            float h0, h1v, h2v, h3;
            unpack2(acc[rr][0], h0, h1v);
            unpack2(acc[rr][1], h2v, h3);
            h0 = fmaxf(h0, 0.f); h1v = fmaxf(h1v, 0.f);
            h2v = fmaxf(h2v, 0.f); h3 = fmaxf(h3, 0.f);
            *(float4*)&bufB[rr * 256 + 8 * l] = make_float4(h0, h0, h1v, h1v);
            *(float4*)&bufB[rr * 256 + 8 * l + 4] = make_float4(h2v, h2v, h3, h3);
        }
        __syncwarp();

        {
            u64 bias0 = *(const u64*)&b2s[4 * l];
            u64 bias1 = *(const u64*)&b2s[4 * l + 2];
#pragma unroll
            for (int rr = 0; rr < 8; rr++) { acc[rr][0] = bias0; acc[rr][1] = bias1; }
        }
#pragma unroll 4
        for (int kp = 0; kp < 64; kp++) {
            ulonglong2 w0 = *(const ulonglong2*)&W2s[(2 * kp) * H_ + 4 * l];
            ulonglong2 w1 = *(const ulonglong2*)&W2s[(2 * kp + 1) * H_ + 4 * l];
#pragma unroll
            for (int rr = 0; rr < 8; rr++) {
                ulonglong2 xq = *(const ulonglong2*)&bufB[rr * 256 + 4 * kp];
                acc[rr][0] = fma2(xq.x, w0.x, acc[rr][0]);
                acc[rr][1] = fma2(xq.x, w0.y, acc[rr][1]);
                acc[rr][0] = fma2(xq.y, w1.x, acc[rr][0]);
                acc[rr][1] = fma2(xq.y, w1.y, acc[rr][1]);
            }
        }
#pragma unroll
        for (int rr = 0; rr < 8; rr++) {
            float h0, h1v, h2v, h3;
            unpack2(acc[rr][0], h0, h1v);
            unpack2(acc[rr][1], h2v, h3);
            h0 = fmaxf(h0, 0.f); h1v = fmaxf(h1v, 0.f);
            h2v = fmaxf(h2v, 0.f); h3 = fmaxf(h3, 0.f);
            *(float4*)&bufA[rr * 256 + 8 * l] = make_float4(h0, h0, h1v, h1v);
            *(float4*)&bufA[rr * 256 + 8 * l + 4] = make_float4(h2v, h2v, h3, h3);
        }
        __syncwarp();

        u64 acc3[8];
        {
            u64 bias = *(const u64*)&b3s[2 * l];
#pragma unroll
            for (int rr = 0; rr < 8; rr++) acc3[rr] = bias;
        }
#pragma unroll 4
        for (int kp = 0; kp < 64; kp++) {
            u64 w0 = *(const u64*)&W3s[(2 * kp) * S_ + 2 * l];
            u64 w1 = *(const u64*)&W3s[(2 * kp + 1) * S_ + 2 * l];
#pragma unroll
            for (int rr = 0; rr < 8; rr++) {
                ulonglong2 xq = *(const ulonglong2*)&bufA[rr * 256 + 4 * kp];
                acc3[rr] = fma2(xq.x, w0, acc3[rr]);
                acc3[rr] = fma2(xq.y, w1, acc3[rr]);
            }
        }

#pragma unroll
        for (int rr = 0; rr < 8; rr++) {
            float z0, z1;
            unpack2(acc3[rr], z0, z1);
            float mx = fmaxf(z0, z1);
#pragma unroll
            for (int off = 16; off; off >>= 1) mx = fmaxf(mx, __shfl_xor_sync(FULL, mx, off));
            float ex = __expf(z0 - mx), ey = __expf(z1 - mx);
            float s = ex + ey;
#pragma unroll
            for (int off = 16; off; off >>= 1) s += __shfl_xor_sync(FULL, s, off);
            float inv = __fdividef(1.f, s);
            *(float2*)&ge[(size_t)(r0 + rr) * S_ + 2 * l] = make_float2(ex * inv, ey * inv);
        }
    }
}

// ---------------- recursions: split-barrier pipelined, 2 warps per chain -------
// 32 blocks x 128 threads. Block b: warps 0-1 = FORWARD chain (batch b),
// warps 2-3 = BACKWARD chain. Warp half h owns states [32h, 32h+32); lane jj
// owns state jj. Per step each warp: computes its half-matvec over its OWN
// input half (warp-locally visible), then bar.sync on the OTHER warp's arrival
// barrier (fast path — the arrival happened one half-matvec ago), finishes
// with the other input half, stores, __syncwarp, bar.arrive on its own barrier.
// The full-barrier release+wait is thereby removed from the critical path.
// Normalization every 2nd step (scale cancels in gamma; LL telescopes).
// Summation structure (P_own + P_oth, sOwn + sOth) matches the R7 passing
// kernel exactly.

#define NARRIVE() asm volatile("bar.arrive %0, 64;" :: "r"(mybar) : "memory")
#define NSYNC()   asm volatile("bar.sync %0, 64;"   :: "r"(otbar) : "memory")

// Half-matvec over inputs [OFF, OFF+32): 8 LDS.128 + 16 fma2, 4 accs x 4 deep.
#define HALF_F(OFF, MP, POUT)                                                   \
    float POUT;                                                                 \
    {                                                                           \
        const ulonglong2* vq = (const ulonglong2*)(svc[p] + (OFF));             \
        u64 A0 = 0, A1 = 0, A2 = 0, A3 = 0;                                     \
        _Pragma("unroll")                                                       \
        for (int n = 0; n < 8; n += 2) {                                        \
            ulonglong2 qa = vq[n], qb = vq[n + 1];                              \
            A0 = fma2(qa.x, MP[2 * n + 0], A0);                                 \
            A1 = fma2(qa.y, MP[2 * n + 1], A1);                                 \
            A2 = fma2(qb.x, MP[2 * n + 2], A2);                                 \
            A3 = fma2(qb.y, MP[2 * n + 3], A3);                                 \
        }                                                                       \
        u64 at = add2(add2(A0, A1), add2(A2, A3));                              \
        float tx, ty;                                                           \
        unpack2(at, tx, ty);                                                    \
        POUT = tx + ty;                                                         \
    }

#define HALF_N(OFF, MP, POUT, SOUT)                                             \
    float POUT, SOUT;                                                           \
    {                                                                           \
        const ulonglong2* vq = (const ulonglong2*)(svc[p] + (OFF));             \
        u64 A0 = 0, A1 = 0, A2 = 0, A3 = 0;                                     \
        u64 s0 = 0, s1 = 0, s2 = 0, s3 = 0;                                     \
        _Pragma("unroll")                                                       \
        for (int n = 0; n < 8; n += 2) {                                        \
            ulonglong2 qa = vq[n], qb = vq[n + 1];                              \
            A0 = fma2(qa.x, MP[2 * n + 0], A0);                                 \
            A1 = fma2(qa.y, MP[2 * n + 1], A1);                                 \
            A2 = fma2(qb.x, MP[2 * n + 2], A2);                                 \
            A3 = fma2(qb.y, MP[2 * n + 3], A3);                                 \
            s0 = add2(s0, qa.x);                                                \
            s1 = add2(s1, qa.y);                                                \
            s2 = add2(s2, qb.x);                                                \
            s3 = add2(s3, qb.y);                                                \
        }                                                                       \
        u64 at = add2(add2(A0, A1), add2(A2, A3));                              \
        u64 st = add2(add2(s0, s1), add2(s2, s3));                              \
        float tx, ty, sx, sy;                                                   \
        unpack2(at, tx, ty);                                                    \
        unpack2(st, sx, sy);                                                    \
        POUT = tx + ty;                                                         \
        SOUT = sx + sy;                                                         \
    }

// ---- forward steps
#define FSF(TT, II, PF)                                                         \
    {                                                                           \
        HALF_F(ownoff, MpOwn, pO)                                               \
        NSYNC();                                                                \
        HALF_F(othoff, MpOth, pX)                                               \
        float a = (pO + pX) * en[II];                                           \
        svc[1 - p][jj] = a;                                                     \
        ab[(size_t)(TT)*S_ + jj] = a;                                           \
        __syncwarp();                                                           \
        NARRIVE();                                                              \
        if (PF) en[II] = eb[(ptrdiff_t)((TT) + 4) * S_ + jj] + EPSV;            \
        p ^= 1;                                                                 \
    }

#define FSN(TT, II, PF)                                                         \
    {                                                                           \
        HALF_N(ownoff, MpOwn, pO, sO)                                           \
        NSYNC();                                                                \
        HALF_N(othoff, MpOth, pX, sX)                                           \
        float csum = sO + sX;                                                   \
        float a = __fdividef((pO + pX) * en[II], csum);                         \
        llacc += (double)__logf(csum);                                          \
        svc[1 - p][jj] = a;                                                     \
        ab[(size_t)(TT)*S_ + jj] = a;                                           \
        __syncwarp();                                                           \
        NARRIVE();                                                              \
        if (PF) en[II] = eb[(ptrdiff_t)((TT) + 4) * S_ + jj] + EPSV;            \
        p ^= 1;                                                                 \
    }

// ---- backward steps
#define BSF(TT, II, PF)                                                         \
    {                                                                           \
        HALF_F(ownoff, MpOwn, pO)                                               \
        NSYNC();                                                                \
        HALF_F(othoff, MpOth, pX)                                               \
        float bt = pO + pX;                                                     \
        bb[(size_t)(TT)*S_ + jj] = bt;                                          \
        svc[1 - p][jj] = bt * en[II];                                           \
        __syncwarp();                                                           \
        NARRIVE();                                                              \
        if (PF) en[II] = eb[(ptrdiff_t)((TT)-4) * S_ + jj] + EPSV;              \
        p ^= 1;                                                                 \
    }

#define BSN(TT, II, PF)                                                         \
    {                                                                           \
        HALF_N(ownoff, MpOwn, pO, sO)                                           \
        NSYNC();                                                                \
        HALF_N(othoff, MpOth, pX, sX)                                           \
        float csum = sO + sX;                                                   \
        float bt = __fdividef(pO + pX, csum);                                   \
        bb[(size_t)(TT)*S_ + jj] = bt;                                          \
        svc[1 - p][jj] = bt * en[II];                                           \
        __syncwarp();                                                           \
        NARRIVE();                                                              \
        if (PF) en[II] = eb[(ptrdiff_t)((TT)-4) * S_ + jj] + EPSV;              \
        p ^= 1;                                                                 \
    }

__global__ void __launch_bounds__(128, 1) recursion_kernel(float* __restrict__ out_ll) {
    __shared__ __align__(16) float sv[2][2][S_];  // [chain][pingpong][state]
    int tid = threadIdx.x;
    int chain = tid >> 6;         // 0 = forward, 1 = backward
    int h = (tid >> 5) & 1;       // warp half within chain
    int lane = tid & 31;
    int jj = h * 32 + lane;       // state owned by this lane
    int b = blockIdx.x;
    int mybar = 1 + chain * 2 + h;
    int otbar = 1 + chain * 2 + (1 - h);
    int ownoff = h * 32;
    int othoff = (1 - h) * 32;
    float (*svc)[S_] = sv[chain];
    const float* eb = g_e_raw + 512 + (size_t)b * T_ * S_;

    // MpOwn[m]: M entries for inputs (ownoff+2m, ownoff+2m+1) feeding state jj.
    u64 MpOwn[16], MpOth[16];
    if (chain == 0) {
#pragma unroll
        for (int k = 0; k < 16; k++) {
            MpOwn[k] = pack2(g_M[(ownoff + 2 * k) * S_ + jj], g_M[(ownoff + 2 * k + 1) * S_ + jj]);
            MpOth[k] = pack2(g_M[(othoff + 2 * k) * S_ + jj], g_M[(othoff + 2 * k + 1) * S_ + jj]);
        }
    } else {
#pragma unroll
        for (int k = 0; k < 16; k++) {
            MpOwn[k] = *(const u64*)&g_M[jj * S_ + ownoff + 2 * k];
            MpOth[k] = *(const u64*)&g_M[jj * S_ + othoff + 2 * k];
        }
    }

    if (chain == 0) {
        // ---------------- forward ----------------
        float* ab = g_alpha + (size_t)b * T_ * S_;
        float a0 = g_pi[jj] * eb[jj];  // t=0 uses raw emission (no EPS)
        sv[0][0][jj] = a0;
        ab[jj] = a0;
        double llacc = 0.0;
        float en[4];
#pragma unroll
        for (int i = 0; i < 4; i++) en[i] = eb[(size_t)(1 + i) * S_ + jj] + EPSV;
        __syncwarp();
        NARRIVE();
        int p = 0;
        for (int g = 0; g < 1023; g++) {
            int t0 = 1 + 4 * g;
            FSF(t0, 0, 1)
            FSN(t0 + 1, 1, 1)
            FSF(t0 + 2, 2, 1)
            FSN(t0 + 3, 3, 1)
        }
        // tail: t = 4093 (free), 4094 (norm), 4095 (free); ring slots 0,1,2
        FSF(T_ - 3, 0, 0)
        FSN(T_ - 2, 1, 0)
        FSF(T_ - 1, 2, 0)

        NSYNC();  // other warp's final half visible
        float fs = 0.f;
#pragma unroll
        for (int k = 0; k < S_; k++) fs += svc[p][k];
        llacc += (double)__logf(fs);
        if (jj == 0) out_ll[b] = (float)llacc;
    } else {
        // ---------------- backward ----------------
        float* bb = g_beta + (size_t)b * T_ * S_;
        bb[(size_t)(T_ - 1) * S_ + jj] = 1.f;
        svc[0][jj] = eb[(size_t)(T_ - 1) * S_ + jj] + EPSV;  // u_{T-1}
        float en[4];
#pragma unroll
        for (int i = 0; i < 4; i++) en[i] = eb[(size_t)(T_ - 2 - i) * S_ + jj] + EPSV;
        __syncwarp();
        NARRIVE();
        int p = 0;
        for (int g = 0; g < 1023; g++) {
            int t0 = T_ - 2 - 4 * g;
            BSF(t0, 0, 1)
            BSN(t0 - 1, 1, 1)
            BSF(t0 - 2, 2, 1)
            BSN(t0 - 3, 3, 1)
        }
        // tail: t = 2 (free), 1 (norm), 0 (free)
        BSF(2, 0, 0)
        BSN(1, 1, 0)
        BSF(0, 2, 0)
    }
}

// ---------------- gamma + marginals (unchanged) ----------------
__global__ void __launch_bounds__(256) gamma_kernel(float* __restrict__ out_probs) {
    int b = blockIdx.x >> 4, chunk = blockIdx.x & 15;
    int w = threadIdx.x >> 5, l = threadIdx.x & 31;
    __shared__ float smarg[8][S_];
    const unsigned FULL = 0xffffffffu;
    float mx = 0.f, my = 0.f;
    int tbase = chunk * 256 + w;
    size_t base = (size_t)b * T_ * S_;
#pragma unroll 4
    for (int k = 0; k < 32; k++) {
        int t = tbase + k * 8;
        size_t idx = base + (size_t)t * S_ + 2 * l;
        float2 va = *(const float2*)&g_alpha[idx];
        float2 vb = *(const float2*)&g_beta[idx];
        float px = va.x * vb.x, py = va.y * vb.y;
        float s = px + py;
#pragma unroll
        for (int off = 16; off; off >>= 1) s += __shfl_xor_sync(FULL, s, off);
        float inv = __fdividef(1.f, s);
        px *= inv; py *= inv;
        *(float2*)&out_probs[idx] = make_float2(px, py);
        mx += px; my += py;
    }
    smarg[w][2 * l] = mx;
    smarg[w][2 * l + 1] = my;
    __syncthreads();
    if (threadIdx.x < S_) {
        float s = 0.f;
#pragma unroll
        for (int ww = 0; ww < 8; ww++) s += smarg[ww][threadIdx.x];
        g_margpart[(size_t)blockIdx.x * S_ + threadIdx.x] = s;
    }
}

__global__ void margreduce_kernel(float* __restrict__ out_marg) {
    int i = blockIdx.x * blockDim.x + threadIdx.x;
    int b = i >> 6, j = i & 63;
    float s = 0.f;
#pragma unroll
    for (int c = 0; c < 16; c++) s += g_margpart[(size_t)(b * 16 + c) * S_ + j];
    out_marg[i] = s * (1.f / (float)T_);
}

// ---------------- launch ----------------
extern "C" void kernel_launch(void* const* d_in, const int* in_sizes, int n_in,
                              void* d_out, int out_size) {
    const float* obs = (const float*)d_in[0];
    const float* W1 = (const float*)d_in[1];
    const float* b1 = (const float*)d_in[2];
    const float* W2 = (const float*)d_in[3];
    const float* b2 = (const float*)d_in[4];
    const float* W3 = (const float*)d_in[5];
    const float* b3 = (const float*)d_in[6];
    const float* ltm = (const float*)d_in[7];
    const float* lip = (const float*)d_in[8];
    const float* lr = (const float*)d_in[9];
    const float* lp = (const float*)d_in[10];

    float* out = (float*)d_out;
    float* out_probs = out;
    float* out_marg = out + (size_t)B_ * T_ * S_;
    float* out_dur = out_marg + (size_t)B_ * S_;
    float* out_ll = out_dur + S_;

    const int smem_bytes = (D_ * H_ + H_ * H_ + H_ * S_ + H_ + H_ + S_ + 4 * 4096) * 4;
    cudaFuncSetAttribute(mlp_kernel, cudaFuncAttributeMaxDynamicSharedMemorySize, smem_bytes);

    setup_kernel<<<1, 64>>>(ltm, lip, lr, lp, out_dur);
    mlp_kernel<<<1024, 128, smem_bytes>>>(obs, W1, b1, W2, b2, W3, b3);
    recursion_kernel<<<32, 128>>>(out_ll);
    gamma_kernel<<<512, 256>>>(out_probs);
    margreduce_kernel<<<8, 256>>>(out_marg);
}

// round 13
// speedup vs baseline: 1.5944x; 1.5944x over previous
#include <cuda_runtime.h>

#define B_ 32
#define T_ 4096
#define D_ 64
#define S_ 64
#define H_ 128
#define EPSV 1e-10f

// g_e padded by 512 floats on each side so prefetch rings load unconditionally.
__device__ __align__(16) float g_e_raw[B_ * T_ * S_ + 1024];
__device__ __align__(16) float g_alpha[B_ * T_ * S_];
__device__ __align__(16) float g_beta[B_ * T_ * S_];
__device__ __align__(16) float g_M[S_ * S_];
__device__ __align__(16) float g_pi[S_];
__device__ __align__(16) float g_margpart[B_ * 16 * S_];

typedef unsigned long long u64;

__device__ __forceinline__ u64 pack2(float x, float y) {
    u64 r; asm("mov.b64 %0, {%1, %2};" : "=l"(r) : "f"(x), "f"(y)); return r;
}
__device__ __forceinline__ void unpack2(u64 v, float& x, float& y) {
    asm("mov.b64 {%0, %1}, %2;" : "=f"(x), "=f"(y) : "l"(v));
}
__device__ __forceinline__ u64 fma2(u64 a, u64 b, u64 c) {
    u64 d; asm("fma.rn.f32x2 %0, %1, %2, %3;" : "=l"(d) : "l"(a), "l"(b), "l"(c)); return d;
}
__device__ __forceinline__ u64 add2(u64 a, u64 b) {
    u64 d; asm("add.rn.f32x2 %0, %1, %2;" : "=l"(d) : "l"(a), "l"(b)); return d;
}

// ---------------- setup ----------------
__global__ void setup_kernel(const float* __restrict__ ltm, const float* __restrict__ lip,
                             const float* __restrict__ lr, const float* __restrict__ lp,
                             float* __restrict__ out_dur) {
    int j = threadIdx.x;
    float row[S_];
    float m = -1e30f;
#pragma unroll
    for (int k = 0; k < S_; k++) {
        float v = (k == j) ? -1e10f : ltm[j * S_ + k];
        row[k] = v;
        m = fmaxf(m, v);
    }
    float s = 0.f;
#pragma unroll
    for (int k = 0; k < S_; k++) { row[k] = expf(row[k] - m); s += row[k]; }
    float inv = 1.f / s;
#pragma unroll
    for (int k = 0; k < S_; k++) g_M[j * S_ + k] = row[k] * inv + EPSV;

    float m2 = -1e30f;
#pragma unroll
    for (int k = 0; k < S_; k++) m2 = fmaxf(m2, lip[k]);
    float s2 = 0.f;
#pragma unroll
    for (int k = 0; k < S_; k++) s2 += expf(lip[k] - m2);
    g_pi[j] = expf(lip[j] - m2) / s2;

    float r = expf(lr[j]);
    float p = 1.f / (1.f + expf(-lp[j]));
    out_dur[j] = r * (1.f - p) / p;
}

// ---------------- probe: shifts ncu capture slot toward recursion ----------------
__global__ void probe_kernel() {}

// ---------------- emission MLP + softmax (unchanged, passing) ----------------
__global__ void __launch_bounds__(128) mlp_kernel(
    const float* __restrict__ obs,
    const float* __restrict__ W1, const float* __restrict__ b1,
    const float* __restrict__ W2, const float* __restrict__ b2,
    const float* __restrict__ W3, const float* __restrict__ b3) {
    extern __shared__ float sm[];
    float* W1s = sm;
    float* W2s = W1s + D_ * H_;
    float* W3s = W2s + H_ * H_;
    float* b1s = W3s + H_ * S_;
    float* b2s = b1s + H_;
    float* b3s = b2s + H_;
    float* bufs = b3s + S_;

    int tid = threadIdx.x;
    for (int i = tid; i < (D_ * H_) / 4; i += 128)
        ((float4*)W1s)[i] = ((const float4*)W1)[i];
    for (int i = tid; i < (H_ * H_) / 4; i += 128)
        ((float4*)W2s)[i] = ((const float4*)W2)[i];
    for (int i = tid; i < (H_ * S_) / 4; i += 128)
        ((float4*)W3s)[i] = ((const float4*)W3)[i];
    if (tid < H_) { b1s[tid] = b1[tid]; b2s[tid] = b2[tid]; }
    if (tid < S_) b3s[tid] = b3[tid];
    __syncthreads();

    int w = tid >> 5, l = tid & 31;
    float* bufA = bufs + w * 4096;
    float* bufB = bufA + 2048;
    const unsigned FULL = 0xffffffffu;
    float* ge = g_e_raw + 512;

    int rowbase = blockIdx.x * 128 + w * 32;

    for (int g = 0; g < 4; g++) {
        int r0 = rowbase + g * 8;
        __syncwarp();
#pragma unroll
        for (int rr = 0; rr < 8; rr++) {
            float2 xv = *(const float2*)&obs[(size_t)(r0 + rr) * D_ + 2 * l];
            *(float4*)&bufA[rr * 128 + 4 * l] = make_float4(xv.x, xv.x, xv.y, xv.y);
        }
        __syncwarp();

        u64 acc[8][2];
        {
            u64 bias0 = *(const u64*)&b1s[4 * l];
            u64 bias1 = *(const u64*)&b1s[4 * l + 2];
#pragma unroll
            for (int rr = 0; rr < 8; rr++) { acc[rr][0] = bias0; acc[rr][1] = bias1; }
        }
#pragma unroll 4
        for (int kp = 0; kp < 32; kp++) {
            ulonglong2 w0 = *(const ulonglong2*)&W1s[(2 * kp) * H_ + 4 * l];
            ulonglong2 w1 = *(const ulonglong2*)&W1s[(2 * kp + 1) * H_ + 4 * l];
#pragma unroll
            for (int rr = 0; rr < 8; rr++) {
                ulonglong2 xq = *(const ulonglong2*)&bufA[rr * 128 + 4 * kp];
                acc[rr][0] = fma2(xq.x, w0.x, acc[rr][0]);
                acc[rr][1] = fma2(xq.x, w0.y, acc[rr][1]);
                acc[rr][0] = fma2(xq.y, w1.x, acc[rr][0]);
                acc[rr][1] = fma2(xq.y, w1.y, acc[rr][1]);
            }
        }
#pragma unroll
        for (int rr = 0; rr < 8; rr++) {
            float h0, h1v, h2v, h3;
            unpack2(acc[rr][0], h0, h1v);
            unpack2(acc[rr][1], h2v, h3);
            h0 = fmaxf(h0, 0.f); h1v = fmaxf(h1v, 0.f);
            h2v = fmaxf(h2v, 0.f); h3 = fmaxf(h3, 0.f);
            *(float4*)&bufB[rr * 256 + 8 * l] = make_float4(h0, h0, h1v, h1v);
            *(float4*)&bufB[rr * 256 + 8 * l + 4] = make_float4(h2v, h2v, h3, h3);
        }
        __syncwarp();

        {
            u64 bias0 = *(const u64*)&b2s[4 * l];
            u64 bias1 = *(const u64*)&b2s[4 * l + 2];
#pragma unroll
            for (int rr = 0; rr < 8; rr++) { acc[rr][0] = bias0; acc[rr][1] = bias1; }
        }
#pragma unroll 4
        for (int kp = 0; kp < 64; kp++) {
            ulonglong2 w0 = *(const ulonglong2*)&W2s[(2 * kp) * H_ + 4 * l];
            ulonglong2 w1 = *(const ulonglong2*)&W2s[(2 * kp + 1) * H_ + 4 * l];
#pragma unroll
            for (int rr = 0; rr < 8; rr++) {
                ulonglong2 xq = *(const ulonglong2*)&bufB[rr * 256 + 4 * kp];
                acc[rr][0] = fma2(xq.x, w0.x, acc[rr][0]);
                acc[rr][1] = fma2(xq.x, w0.y, acc[rr][1]);
                acc[rr][0] = fma2(xq.y, w1.x, acc[rr][0]);
                acc[rr][1] = fma2(xq.y, w1.y, acc[rr][1]);
            }
        }
#pragma unroll
        for (int rr = 0; rr < 8; rr++) {
            float h0, h1v, h2v, h3;
            unpack2(acc[rr][0], h0, h1v);
            unpack2(acc[rr][1], h2v, h3);
            h0 = fmaxf(h0, 0.f); h1v = fmaxf(h1v, 0.f);
            h2v = fmaxf(h2v, 0.f); h3 = fmaxf(h3, 0.f);
            *(float4*)&bufA[rr * 256 + 8 * l] = make_float4(h0, h0, h1v, h1v);
            *(float4*)&bufA[rr * 256 + 8 * l + 4] = make_float4(h2v, h2v, h3, h3);
        }
        __syncwarp();

        u64 acc3[8];
        {
            u64 bias = *(const u64*)&b3s[2 * l];
#pragma unroll
            for (int rr = 0; rr < 8; rr++) acc3[rr] = bias;
        }
#pragma unroll 4
        for (int kp = 0; kp < 64; kp++) {
            u64 w0 = *(const u64*)&W3s[(2 * kp) * S_ + 2 * l];
            u64 w1 = *(const u64*)&W3s[(2 * kp + 1) * S_ + 2 * l];
#pragma unroll
            for (int rr = 0; rr < 8; rr++) {
                ulonglong2 xq = *(const ulonglong2*)&bufA[rr * 256 + 4 * kp];
                acc3[rr] = fma2(xq.x, w0, acc3[rr]);
                acc3[rr] = fma2(xq.y, w1, acc3[rr]);
            }
        }

#pragma unroll
        for (int rr = 0; rr < 8; rr++) {
            float z0, z1;
            unpack2(acc3[rr], z0, z1);
            float mx = fmaxf(z0, z1);
#pragma unroll
            for (int off = 16; off; off >>= 1) mx = fmaxf(mx, __shfl_xor_sync(FULL, mx, off));
            float ex = __expf(z0 - mx), ey = __expf(z1 - mx);
            float s = ex + ey;
#pragma unroll
            for (int off = 16; off; off >>= 1) s += __shfl_xor_sync(FULL, s, off);
            float inv = __fdividef(1.f, s);
            *(float2*)&ge[(size_t)(r0 + rr) * S_ + 2 * l] = make_float2(ex * inv, ey * inv);
        }
    }
}

// ---------------- recursions: R6 structure, normalize every 4th step -----------
// 32 blocks x 128 threads. Block b: tids 0-63 = FORWARD chain batch b (bar 1),
// tids 64-127 = BACKWARD chain batch b (bar 2). Lane group j = tid&63 owns
// state j. Normalization every 4th step: the per-step scale cancels exactly in
// gamma (per-(b,t) renormalization) and LL telescopes as sum(log csum at norm
// events) + log(sum v_final) — cadence-independent. Free steps skip csum,
// divide, and log. Branch-free hot loop: 4x unroll (3 free + 1 norm), peeled
// free tail, 4-deep padded prefetch ring.

#define NBAR() asm volatile("bar.sync %0, 64;" :: "r"(barid) : "memory")

// Full 64-input matvec: v4[0..15], Mp[0..31].
#define MATV_F(TOUT)                                                             \
    float TOUT;                                                                  \
    {                                                                            \
        const ulonglong2* v4 = (const ulonglong2*)svc[p];                        \
        u64 A0 = 0, A1 = 0, A2 = 0, A3 = 0;                                      \
        _Pragma("unroll")                                                        \
        for (int n = 0; n < 16; n += 2) {                                        \
            ulonglong2 qa = v4[n], qb = v4[n + 1];                               \
            A0 = fma2(qa.x, Mp[2 * n + 0], A0);                                  \
            A1 = fma2(qa.y, Mp[2 * n + 1], A1);                                  \
            A2 = fma2(qb.x, Mp[2 * n + 2], A2);                                  \
            A3 = fma2(qb.y, Mp[2 * n + 3], A3);                                  \
        }                                                                        \
        u64 at = add2(add2(A0, A1), add2(A2, A3));                               \
        float tx, ty;                                                            \
        unpack2(at, tx, ty);                                                     \
        TOUT = tx + ty;                                                          \
    }

#define MATV_N(TOUT, SOUT)                                                       \
    float TOUT, SOUT;                                                            \
    {                                                                            \
        const ulonglong2* v4 = (const ulonglong2*)svc[p];                        \
        u64 A0 = 0, A1 = 0, A2 = 0, A3 = 0;                                      \
        u64 s0 = 0, s1 = 0, s2 = 0, s3 = 0;                                      \
        _Pragma("unroll")                                                        \
        for (int n = 0; n < 16; n += 2) {                                        \
            ulonglong2 qa = v4[n], qb = v4[n + 1];                               \
            A0 = fma2(qa.x, Mp[2 * n + 0], A0);                                  \
            A1 = fma2(qa.y, Mp[2 * n + 1], A1);                                  \
            A2 = fma2(qb.x, Mp[2 * n + 2], A2);                                  \
            A3 = fma2(qb.y, Mp[2 * n + 3], A3);                                  \
            s0 = add2(s0, qa.x);                                                 \
            s1 = add2(s1, qa.y);                                                 \
            s2 = add2(s2, qb.x);                                                 \
            s3 = add2(s3, qb.y);                                                 \
        }                                                                        \
        u64 at = add2(add2(A0, A1), add2(A2, A3));                               \
        u64 st = add2(add2(s0, s1), add2(s2, s3));                               \
        float tx, ty, sx, sy;                                                    \
        unpack2(at, tx, ty);                                                     \
        unpack2(st, sx, sy);                                                     \
        TOUT = tx + ty;                                                          \
        SOUT = sx + sy;                                                          \
    }

// ---- forward steps
#define FSTEP_F(TT, II, PF)                                                      \
    {                                                                            \
        MATV_F(tA)                                                               \
        float a = tA * en[II];                                                   \
        svc[1 - p][j] = a;                                                       \
        ab[(size_t)(TT)*S_ + j] = a;                                             \
        if (PF) en[II] = eb[(ptrdiff_t)((TT) + 4) * S_ + j] + EPSV;              \
        NBAR();                                                                  \
        p ^= 1;                                                                  \
    }

#define FSTEP_N(TT, II, PF)                                                      \
    {                                                                            \
        MATV_N(tA, csum)                                                         \
        float a = __fdividef(tA * en[II], csum);                                 \
        llacc += (double)__logf(csum);                                           \
        svc[1 - p][j] = a;                                                       \
        ab[(size_t)(TT)*S_ + j] = a;                                             \
        if (PF) en[II] = eb[(ptrdiff_t)((TT) + 4) * S_ + j] + EPSV;              \
        NBAR();                                                                  \
        p ^= 1;                                                                  \
    }

// ---- backward steps
#define BSTEP_F(TT, II, PF)                                                      \
    {                                                                            \
        MATV_F(tA)                                                               \
        bb[(size_t)(TT)*S_ + j] = tA;                                            \
        svc[1 - p][j] = tA * en[II];                                             \
        if (PF) en[II] = eb[(ptrdiff_t)((TT)-4) * S_ + j] + EPSV;                \
        NBAR();                                                                  \
        p ^= 1;                                                                  \
    }

#define BSTEP_N(TT, II, PF)                                                      \
    {                                                                            \
        MATV_N(tA, csum)                                                         \
        float bt = __fdividef(tA, csum);                                         \
        bb[(size_t)(TT)*S_ + j] = bt;                                            \
        svc[1 - p][j] = bt * en[II];                                             \
        if (PF) en[II] = eb[(ptrdiff_t)((TT)-4) * S_ + j] + EPSV;                \
        NBAR();                                                                  \
        p ^= 1;                                                                  \
    }

__global__ void __launch_bounds__(128, 1) recursion_kernel(float* __restrict__ out_ll) {
    __shared__ __align__(16) float sv[2][2][S_];  // [chain][pingpong][state]
    int tid = threadIdx.x;
    int half = tid >> 6;   // 0 = forward, 1 = backward
    int j = tid & 63;      // state owned by this lane
    int b = blockIdx.x;
    int barid = 1 + half;
    float (*svc)[S_] = sv[half];
    const float* eb = g_e_raw + 512 + (size_t)b * T_ * S_;

    // Mp[k]: M entries for input states (2k, 2k+1) feeding output state j.
    //   fwd: column j of M;  bwd: row j of M.
    u64 Mp[32];
    if (half == 0) {
#pragma unroll
        for (int k = 0; k < 32; k++)
            Mp[k] = pack2(g_M[(2 * k) * S_ + j], g_M[(2 * k + 1) * S_ + j]);
    } else {
#pragma unroll
        for (int k = 0; k < 32; k++)
            Mp[k] = *(const u64*)&g_M[j * S_ + 2 * k];
    }

    if (half == 0) {
        // ---------------- forward ----------------
        float* ab = g_alpha + (size_t)b * T_ * S_;
        float a0 = g_pi[j] * eb[j];  // t=0 uses raw emission (no EPS)
        svc[0][j] = a0;
        ab[j] = a0;
        double llacc = 0.0;
        float en[4];
#pragma unroll
        for (int i = 0; i < 4; i++) en[i] = eb[(size_t)(1 + i) * S_ + j] + EPSV;
        NBAR();
        int p = 0;
        for (int g = 0; g < 1023; g++) {
            int t0 = 1 + 4 * g;  // steps t0..t0+3; norm at t0+3 (t % 4 == 0)
            FSTEP_F(t0, 0, 1)
            FSTEP_F(t0 + 1, 1, 1)
            FSTEP_F(t0 + 2, 2, 1)
            FSTEP_N(t0 + 3, 3, 1)
        }
        // tail: t = 4093, 4094, 4095 — all free (ring slots 0,1,2)
        FSTEP_F(T_ - 3, 0, 0)
        FSTEP_F(T_ - 2, 1, 0)
        FSTEP_F(T_ - 1, 2, 0)

        float fs = 0.f;
#pragma unroll
        for (int k = 0; k < S_; k++) fs += svc[p][k];
        llacc += (double)__logf(fs);
        if (j == 0) out_ll[b] = (float)llacc;
    } else {
        // ---------------- backward ----------------
        float* bb = g_beta + (size_t)b * T_ * S_;
        bb[(size_t)(T_ - 1) * S_ + j] = 1.f;
        svc[0][j] = eb[(size_t)(T_ - 1) * S_ + j] + EPSV;  // u_{T-1}
        float en[4];
#pragma unroll
        for (int i = 0; i < 4; i++) en[i] = eb[(size_t)(T_ - 2 - i) * S_ + j] + EPSV;
        NBAR();
        int p = 0;
        for (int g = 0; g < 1023; g++) {
            int t0 = T_ - 2 - 4 * g;  // steps t0..t0-3; norm at t0-3
            BSTEP_F(t0, 0, 1)
            BSTEP_F(t0 - 1, 1, 1)
            BSTEP_F(t0 - 2, 2, 1)
            BSTEP_N(t0 - 3, 3, 1)
        }
        // tail: t = 2, 1, 0 — all free (ring slots 0,1,2)
        BSTEP_F(2, 0, 0)
        BSTEP_F(1, 1, 0)
        BSTEP_F(0, 2, 0)
    }
}

// ---------------- gamma + marginals (unchanged) ----------------
__global__ void __launch_bounds__(256) gamma_kernel(float* __restrict__ out_probs) {
    int b = blockIdx.x >> 4, chunk = blockIdx.x & 15;
    int w = threadIdx.x >> 5, l = threadIdx.x & 31;
    __shared__ float smarg[8][S_];
    const unsigned FULL = 0xffffffffu;
    float mx = 0.f, my = 0.f;
    int tbase = chunk * 256 + w;
    size_t base = (size_t)b * T_ * S_;
#pragma unroll 4
    for (int k = 0; k < 32; k++) {
        int t = tbase + k * 8;
        size_t idx = base + (size_t)t * S_ + 2 * l;
        float2 va = *(const float2*)&g_alpha[idx];
        float2 vb = *(const float2*)&g_beta[idx];
        float px = va.x * vb.x, py = va.y * vb.y;
        float s = px + py;
#pragma unroll
        for (int off = 16; off; off >>= 1) s += __shfl_xor_sync(FULL, s, off);
        float inv = __fdividef(1.f, s);
        px *= inv; py *= inv;
        *(float2*)&out_probs[idx] = make_float2(px, py);
        mx += px; my += py;
    }
    smarg[w][2 * l] = mx;
    smarg[w][2 * l + 1] = my;
    __syncthreads();
    if (threadIdx.x < S_) {
        float s = 0.f;
#pragma unroll
        for (int ww = 0; ww < 8; ww++) s += smarg[ww][threadIdx.x];
        g_margpart[(size_t)blockIdx.x * S_ + threadIdx.x] = s;
    }
}

__global__ void margreduce_kernel(float* __restrict__ out_marg) {
    int i = blockIdx.x * blockDim.x + threadIdx.x;
    int b = i >> 6, j = i & 63;
    float s = 0.f;
#pragma unroll
    for (int c = 0; c < 16; c++) s += g_margpart[(size_t)(b * 16 + c) * S_ + j];
    out_marg[i] = s * (1.f / (float)T_);
}

// ---------------- launch ----------------
extern "C" void kernel_launch(void* const* d_in, const int* in_sizes, int n_in,
                              void* d_out, int out_size) {
    const float* obs = (const float*)d_in[0];
    const float* W1 = (const float*)d_in[1];
    const float* b1 = (const float*)d_in[2];
    const float* W2 = (const float*)d_in[3];
    const float* b2 = (const float*)d_in[4];
    const float* W3 = (const float*)d_in[5];
    const float* b3 = (const float*)d_in[6];
    const float* ltm = (const float*)d_in[7];
    const float* lip = (const float*)d_in[8];
    const float* lr = (const float*)d_in[9];
    const float* lp = (const float*)d_in[10];

    float* out = (float*)d_out;
    float* out_probs = out;
    float* out_marg = out + (size_t)B_ * T_ * S_;
    float* out_dur = out_marg + (size_t)B_ * S_;
    float* out_ll = out_dur + S_;

    const int smem_bytes = (D_ * H_ + H_ * H_ + H_ * S_ + H_ + H_ + S_ + 4 * 4096) * 4;
    cudaFuncSetAttribute(mlp_kernel, cudaFuncAttributeMaxDynamicSharedMemorySize, smem_bytes);

    setup_kernel<<<1, 64>>>(ltm, lip, lr, lp, out_dur);
    mlp_kernel<<<1024, 128, smem_bytes>>>(obs, W1, b1, W2, b2, W3, b3);
    probe_kernel<<<1, 32>>>();  // shifts ncu capture slot; recursion now at index 3
    recursion_kernel<<<32, 128>>>(out_ll);
    gamma_kernel<<<512, 256>>>(out_probs);
    margreduce_kernel<<<8, 256>>>(out_marg);
}

// round 14
// speedup vs baseline: 3.3425x; 2.0964x over previous
#include <cuda_runtime.h>

#define B_ 32
#define T_ 4096
#define D_ 64
#define S_ 64
#define H_ 128
#define EPSV 1e-10f
#define LSEG 256
#define WSEG 32
#define NSEG 16

// g_e padded by 512 floats on each side so prefetch rings load unconditionally.
__device__ __align__(16) float g_e_raw[B_ * T_ * S_ + 1024];
__device__ __align__(16) float g_alpha[B_ * T_ * S_];
__device__ __align__(16) float g_beta[B_ * T_ * S_];
__device__ __align__(16) float g_M[S_ * S_];
__device__ __align__(16) float g_pi[S_];
__device__ __align__(16) float g_margpart[B_ * 16 * S_];
__device__ double g_llpart[B_ * NSEG];

typedef unsigned long long u64;

__device__ __forceinline__ u64 pack2(float x, float y) {
    u64 r; asm("mov.b64 %0, {%1, %2};" : "=l"(r) : "f"(x), "f"(y)); return r;
}
__device__ __forceinline__ void unpack2(u64 v, float& x, float& y) {
    asm("mov.b64 {%0, %1}, %2;" : "=f"(x), "=f"(y) : "l"(v));
}
__device__ __forceinline__ u64 fma2(u64 a, u64 b, u64 c) {
    u64 d; asm("fma.rn.f32x2 %0, %1, %2, %3;" : "=l"(d) : "l"(a), "l"(b), "l"(c)); return d;
}
__device__ __forceinline__ u64 add2(u64 a, u64 b) {
    u64 d; asm("add.rn.f32x2 %0, %1, %2;" : "=l"(d) : "l"(a), "l"(b)); return d;
}

// ---------------- setup ----------------
__global__ void setup_kernel(const float* __restrict__ ltm, const float* __restrict__ lip,
                             const float* __restrict__ lr, const float* __restrict__ lp,
                             float* __restrict__ out_dur) {
    int j = threadIdx.x;
    float row[S_];
    float m = -1e30f;
#pragma unroll
    for (int k = 0; k < S_; k++) {
        float v = (k == j) ? -1e10f : ltm[j * S_ + k];
        row[k] = v;
        m = fmaxf(m, v);
    }
    float s = 0.f;
#pragma unroll
    for (int k = 0; k < S_; k++) { row[k] = expf(row[k] - m); s += row[k]; }
    float inv = 1.f / s;
#pragma unroll
    for (int k = 0; k < S_; k++) g_M[j * S_ + k] = row[k] * inv + EPSV;

    float m2 = -1e30f;
#pragma unroll
    for (int k = 0; k < S_; k++) m2 = fmaxf(m2, lip[k]);
    float s2 = 0.f;
#pragma unroll
    for (int k = 0; k < S_; k++) s2 += expf(lip[k] - m2);
    g_pi[j] = expf(lip[j] - m2) / s2;

    float r = expf(lr[j]);
    float p = 1.f / (1.f + expf(-lp[j]));
    out_dur[j] = r * (1.f - p) / p;
}

// ---------------- probe: keeps ncu capture slot near recursion ----------------
__global__ void probe_kernel() {}

// ---------------- emission MLP + softmax (unchanged, passing) ----------------
__global__ void __launch_bounds__(128) mlp_kernel(
    const float* __restrict__ obs,
    const float* __restrict__ W1, const float* __restrict__ b1,
    const float* __restrict__ W2, const float* __restrict__ b2,
    const float* __restrict__ W3, const float* __restrict__ b3) {
    extern __shared__ float sm[];
    float* W1s = sm;
    float* W2s = W1s + D_ * H_;
    float* W3s = W2s + H_ * H_;
    float* b1s = W3s + H_ * S_;
    float* b2s = b1s + H_;
    float* b3s = b2s + H_;
    float* bufs = b3s + S_;

    int tid = threadIdx.x;
    for (int i = tid; i < (D_ * H_) / 4; i += 128)
        ((float4*)W1s)[i] = ((const float4*)W1)[i];
    for (int i = tid; i < (H_ * H_) / 4; i += 128)
        ((float4*)W2s)[i] = ((const float4*)W2)[i];
    for (int i = tid; i < (H_ * S_) / 4; i += 128)
        ((float4*)W3s)[i] = ((const float4*)W3)[i];
    if (tid < H_) { b1s[tid] = b1[tid]; b2s[tid] = b2[tid]; }
    if (tid < S_) b3s[tid] = b3[tid];
    __syncthreads();

    int w = tid >> 5, l = tid & 31;
    float* bufA = bufs + w * 4096;
    float* bufB = bufA + 2048;
    const unsigned FULL = 0xffffffffu;
    float* ge = g_e_raw + 512;

    int rowbase = blockIdx.x * 128 + w * 32;

    for (int g = 0; g < 4; g++) {
        int r0 = rowbase + g * 8;
        __syncwarp();
#pragma unroll
        for (int rr = 0; rr < 8; rr++) {
            float2 xv = *(const float2*)&obs[(size_t)(r0 + rr) * D_ + 2 * l];
            *(float4*)&bufA[rr * 128 + 4 * l] = make_float4(xv.x, xv.x, xv.y, xv.y);
        }
        __syncwarp();

        u64 acc[8][2];
        {
            u64 bias0 = *(const u64*)&b1s[4 * l];
            u64 bias1 = *(const u64*)&b1s[4 * l + 2];
#pragma unroll
            for (int rr = 0; rr < 8; rr++) { acc[rr][0] = bias0; acc[rr][1] = bias1; }
        }
#pragma unroll 4
        for (int kp = 0; kp < 32; kp++) {
            ulonglong2 w0 = *(const ulonglong2*)&W1s[(2 * kp) * H_ + 4 * l];
            ulonglong2 w1 = *(const ulonglong2*)&W1s[(2 * kp + 1) * H_ + 4 * l];
#pragma unroll
            for (int rr = 0; rr < 8; rr++) {
                ulonglong2 xq = *(const ulonglong2*)&bufA[rr * 128 + 4 * kp];
                acc[rr][0] = fma2(xq.x, w0.x, acc[rr][0]);
                acc[rr][1] = fma2(xq.x, w0.y, acc[rr][1]);
                acc[rr][0] = fma2(xq.y, w1.x, acc[rr][0]);
                acc[rr][1] = fma2(xq.y, w1.y, acc[rr][1]);
            }
        }
#pragma unroll
        for (int rr = 0; rr < 8; rr++) {
            float h0, h1v, h2v, h3;
            unpack2(acc[rr][0], h0, h1v);
            unpack2(acc[rr][1], h2v, h3);
            h0 = fmaxf(h0, 0.f); h1v = fmaxf(h1v, 0.f);
            h2v = fmaxf(h2v, 0.f); h3 = fmaxf(h3, 0.f);
            *(float4*)&bufB[rr * 256 + 8 * l] = make_float4(h0, h0, h1v, h1v);
            *(float4*)&bufB[rr * 256 + 8 * l + 4] = make_float4(h2v, h2v, h3, h3);
        }
        __syncwarp();

        {
            u64 bias0 = *(const u64*)&b2s[4 * l];
            u64 bias1 = *(const u64*)&b2s[4 * l + 2];
#pragma unroll
            for (int rr = 0; rr < 8; rr++) { acc[rr][0] = bias0; acc[rr][1] = bias1; }
        }
#pragma unroll 4
        for (int kp = 0; kp < 64; kp++) {
            ulonglong2 w0 = *(const ulonglong2*)&W2s[(2 * kp) * H_ + 4 * l];
            ulonglong2 w1 = *(const ulonglong2*)&W2s[(2 * kp + 1) * H_ + 4 * l];
#pragma unroll
            for (int rr = 0; rr < 8; rr++) {
                ulonglong2 xq = *(const ulonglong2*)&bufB[rr * 256 + 4 * kp];
                acc[rr][0] = fma2(xq.x, w0.x, acc[rr][0]);
                acc[rr][1] = fma2(xq.x, w0.y, acc[rr][1]);
                acc[rr][0] = fma2(xq.y, w1.x, acc[rr][0]);
                acc[rr][1] = fma2(xq.y, w1.y, acc[rr][1]);
            }
        }
#pragma unroll
        for (int rr = 0; rr < 8; rr++) {
            float h0, h1v, h2v, h3;
            unpack2(acc[rr][0], h0, h1v);
            unpack2(acc[rr][1], h2v, h3);
            h0 = fmaxf(h0, 0.f); h1v = fmaxf(h1v, 0.f);
            h2v = fmaxf(h2v, 0.f); h3 = fmaxf(h3, 0.f);
            *(float4*)&bufA[rr * 256 + 8 * l] = make_float4(h0, h0, h1v, h1v);
            *(float4*)&bufA[rr * 256 + 8 * l + 4] = make_float4(h2v, h2v, h3, h3);
        }
        __syncwarp();

        u64 acc3[8];
        {
            u64 bias = *(const u64*)&b3s[2 * l];
#pragma unroll
            for (int rr = 0; rr < 8; rr++) acc3[rr] = bias;
        }
#pragma unroll 4
        for (int kp = 0; kp < 64; kp++) {
            u64 w0 = *(const u64*)&W3s[(2 * kp) * S_ + 2 * l];
            u64 w1 = *(const u64*)&W3s[(2 * kp + 1) * S_ + 2 * l];
#pragma unroll
            for (int rr = 0; rr < 8; rr++) {
                ulonglong2 xq = *(const ulonglong2*)&bufA[rr * 256 + 4 * kp];
                acc3[rr] = fma2(xq.x, w0, acc3[rr]);
                acc3[rr] = fma2(xq.y, w1, acc3[rr]);
            }
        }

#pragma unroll
        for (int rr = 0; rr < 8; rr++) {
            float z0, z1;
            unpack2(acc3[rr], z0, z1);
            float mx = fmaxf(z0, z1);
#pragma unroll
            for (int off = 16; off; off >>= 1) mx = fmaxf(mx, __shfl_xor_sync(FULL, mx, off));
            float ex = __expf(z0 - mx), ey = __expf(z1 - mx);
            float s = ex + ey;
#pragma unroll
            for (int off = 16; off; off >>= 1) s += __shfl_xor_sync(FULL, s, off);
            float inv = __fdividef(1.f, s);
            *(float2*)&ge[(size_t)(r0 + rr) * S_ + 2 * l] = make_float2(ex * inv, ey * inv);
        }
    }
}

// ---------------- segmented recursions -----------------------------------------
// 512 blocks x 128 threads: block = (batch b, segment s). tids 0-63 = FORWARD
// (bar 1), tids 64-127 = BACKWARD (bar 2). Segments of LSEG=256 steps run in
// PARALLEL; each non-initial segment warms up WSEG=32 steps from a uniform
// vector (Hilbert-metric contraction of the near-uniform M makes the state
// forget its init in ~10 steps; 32 is large margin). Per-(b,t) row scales of
// alpha/beta are arbitrary (gamma renormalizes each row). LL telescopes per
// segment: sum(log D at norm steps) + log(sum v_end) - log(sum v_entry);
// segment 0 skips the entry subtraction (supplies the log sum(pi*e0) term).
// Per-step arithmetic identical to the R13 passing kernel; cadence-4 norm.

#define NBAR() asm volatile("bar.sync %0, 64;" :: "r"(barid) : "memory")

#define MATV_F(TOUT)                                                             \
    float TOUT;                                                                  \
    {                                                                            \
        const ulonglong2* v4 = (const ulonglong2*)svc[p];                        \
        u64 A0 = 0, A1 = 0, A2 = 0, A3 = 0;                                      \
        _Pragma("unroll")                                                        \
        for (int n = 0; n < 16; n += 2) {                                        \
            ulonglong2 qa = v4[n], qb = v4[n + 1];                               \
            A0 = fma2(qa.x, Mp[2 * n + 0], A0);                                  \
            A1 = fma2(qa.y, Mp[2 * n + 1], A1);                                  \
            A2 = fma2(qb.x, Mp[2 * n + 2], A2);                                  \
            A3 = fma2(qb.y, Mp[2 * n + 3], A3);                                  \
        }                                                                        \
        u64 at = add2(add2(A0, A1), add2(A2, A3));                               \
        float tx, ty;                                                            \
        unpack2(at, tx, ty);                                                     \
        TOUT = tx + ty;                                                          \
    }

#define MATV_N(TOUT, SOUT)                                                       \
    float TOUT, SOUT;                                                            \
    {                                                                            \
        const ulonglong2* v4 = (const ulonglong2*)svc[p];                        \
        u64 A0 = 0, A1 = 0, A2 = 0, A3 = 0;                                      \
        u64 s0 = 0, s1 = 0, s2 = 0, s3 = 0;                                      \
        _Pragma("unroll")                                                        \
        for (int n = 0; n < 16; n += 2) {                                        \
            ulonglong2 qa = v4[n], qb = v4[n + 1];                               \
            A0 = fma2(qa.x, Mp[2 * n + 0], A0);                                  \
            A1 = fma2(qa.y, Mp[2 * n + 1], A1);                                  \
            A2 = fma2(qb.x, Mp[2 * n + 2], A2);                                  \
            A3 = fma2(qb.y, Mp[2 * n + 3], A3);                                  \
            s0 = add2(s0, qa.x);                                                 \
            s1 = add2(s1, qa.y);                                                 \
            s2 = add2(s2, qb.x);                                                 \
            s3 = add2(s3, qb.y);                                                 \
        }                                                                        \
        u64 at = add2(add2(A0, A1), add2(A2, A3));                               \
        u64 st = add2(add2(s0, s1), add2(s2, s3));                               \
        float tx, ty, sx, sy;                                                    \
        unpack2(at, tx, ty);                                                     \
        unpack2(st, sx, sy);                                                     \
        TOUT = tx + ty;                                                          \
        SOUT = sx + sy;                                                          \
    }

// ---- forward owned steps (write alpha; norm logs into llacc)
#define FSTEP_F(TT, II)                                                          \
    {                                                                            \
        MATV_F(tA)                                                               \
        float a = tA * en[II];                                                   \
        svc[1 - p][j] = a;                                                       \
        ab[(size_t)(TT)*S_ + j] = a;                                             \
        en[II] = eb[(ptrdiff_t)((TT) + 4) * S_ + j] + EPSV;                      \
        NBAR();                                                                  \
        p ^= 1;                                                                  \
    }

#define FSTEP_N(TT, II)                                                          \
    {                                                                            \
        MATV_N(tA, csum)                                                         \
        float a = __fdividef(tA * en[II], csum);                                 \
        llacc += (double)__logf(csum);                                           \
        svc[1 - p][j] = a;                                                       \
        ab[(size_t)(TT)*S_ + j] = a;                                             \
        en[II] = eb[(ptrdiff_t)((TT) + 4) * S_ + j] + EPSV;                      \
        NBAR();                                                                  \
        p ^= 1;                                                                  \
    }

// ---- forward warm-up steps (no writes, no logs)
#define FSTEP_WF(TT, II)                                                         \
    {                                                                            \
        MATV_F(tA)                                                               \
        svc[1 - p][j] = tA * en[II];                                             \
        en[II] = eb[(ptrdiff_t)((TT) + 4) * S_ + j] + EPSV;                      \
        NBAR();                                                                  \
        p ^= 1;                                                                  \
    }

#define FSTEP_WN(TT, II)                                                         \
    {                                                                            \
        MATV_N(tA, csum)                                                         \
        svc[1 - p][j] = __fdividef(tA * en[II], csum);                           \
        en[II] = eb[(ptrdiff_t)((TT) + 4) * S_ + j] + EPSV;                      \
        NBAR();                                                                  \
        p ^= 1;                                                                  \
    }

// ---- backward owned steps (write beta)
#define BSTEP_F(TT, II)                                                          \
    {                                                                            \
        MATV_F(tA)                                                               \
        bb[(size_t)(TT)*S_ + j] = tA;                                            \
        svc[1 - p][j] = tA * en[II];                                             \
        en[II] = eb[(ptrdiff_t)((TT)-4) * S_ + j] + EPSV;                        \
        NBAR();                                                                  \
        p ^= 1;                                                                  \
    }

#define BSTEP_N(TT, II)                                                          \
    {                                                                            \
        MATV_N(tA, csum)                                                         \
        float bt = __fdividef(tA, csum);                                         \
        bb[(size_t)(TT)*S_ + j] = bt;                                            \
        svc[1 - p][j] = bt * en[II];                                             \
        en[II] = eb[(ptrdiff_t)((TT)-4) * S_ + j] + EPSV;                        \
        NBAR();                                                                  \
        p ^= 1;                                                                  \
    }

// ---- backward warm-up steps (no writes)
#define BSTEP_WF(TT, II)                                                         \
    {                                                                            \
        MATV_F(tA)                                                               \
        svc[1 - p][j] = tA * en[II];                                             \
        en[II] = eb[(ptrdiff_t)((TT)-4) * S_ + j] + EPSV;                        \
        NBAR();                                                                  \
        p ^= 1;                                                                  \
    }

#define BSTEP_WN(TT, II)                                                         \
    {                                                                            \
        MATV_N(tA, csum)                                                         \
        float bt = __fdividef(tA, csum);                                         \
        svc[1 - p][j] = bt * en[II];                                             \
        en[II] = eb[(ptrdiff_t)((TT)-4) * S_ + j] + EPSV;                        \
        NBAR();                                                                  \
        p ^= 1;                                                                  \
    }

__global__ void __launch_bounds__(128, 1) recursion_kernel() {
    __shared__ __align__(16) float sv[2][2][S_];  // [chain][pingpong][state]
    int tid = threadIdx.x;
    int half = tid >> 6;   // 0 = forward, 1 = backward
    int j = tid & 63;      // state owned by this lane
    int b = blockIdx.x & 31;
    int s = blockIdx.x >> 5;  // segment 0..NSEG-1
    int barid = 1 + half;
    float (*svc)[S_] = sv[half];
    const float* eb = g_e_raw + 512 + (size_t)b * T_ * S_;

    u64 Mp[32];
    if (half == 0) {
#pragma unroll
        for (int k = 0; k < 32; k++)
            Mp[k] = pack2(g_M[(2 * k) * S_ + j], g_M[(2 * k + 1) * S_ + j]);
    } else {
#pragma unroll
        for (int k = 0; k < 32; k++)
            Mp[k] = *(const u64*)&g_M[j * S_ + 2 * k];
    }

    if (half == 0) {
        // ---------------- forward segment ----------------
        float* ab = g_alpha + (size_t)b * T_ * S_;
        double llacc = 0.0;
        float en[4];
        int p = 0;
        if (s == 0) {
            float a0 = g_pi[j] * eb[j];  // t=0: raw emission (no EPS)
            svc[0][j] = a0;
            ab[j] = a0;
#pragma unroll
            for (int i = 0; i < 4; i++) en[i] = eb[(size_t)(1 + i) * S_ + j] + EPSV;
            NBAR();
            // owned: t = 1..255 (63 groups + 3 tail)
            for (int g = 0; g < 63; g++) {
                int t0 = 1 + 4 * g;
                FSTEP_F(t0, 0)
                FSTEP_F(t0 + 1, 1)
                FSTEP_F(t0 + 2, 2)
                FSTEP_N(t0 + 3, 3)
            }
            FSTEP_F(LSEG - 3, 0)
            FSTEP_F(LSEG - 2, 1)
            FSTEP_F(LSEG - 1, 2)
        } else {
            int t0s = s * LSEG;
            svc[0][j] = 1.0f / 64.0f;  // uniform warm-up init
#pragma unroll
            for (int i = 0; i < 4; i++)
                en[i] = eb[(size_t)(t0s - WSEG + i) * S_ + j] + EPSV;
            NBAR();
            // warm-up: t = t0s-32 .. t0s-1 (8 groups)
            for (int g = 0; g < WSEG / 4; g++) {
                int t0 = t0s - WSEG + 4 * g;
                FSTEP_WF(t0, 0)
                FSTEP_WF(t0 + 1, 1)
                FSTEP_WF(t0 + 2, 2)
                FSTEP_WN(t0 + 3, 3)
            }
            // entry sum (reads svc[p]; owned steps write svc[1-p] first — safe)
            float fsE = 0.f;
#pragma unroll
            for (int k = 0; k < S_; k++) fsE += svc[p][k];
            llacc = -(double)__logf(fsE);
            // owned: t = t0s .. t0s+255 (64 groups)
            for (int g = 0; g < 64; g++) {
                int t0 = t0s + 4 * g;
                FSTEP_F(t0, 0)
                FSTEP_F(t0 + 1, 1)
                FSTEP_F(t0 + 2, 2)
                FSTEP_N(t0 + 3, 3)
            }
        }
        float fs = 0.f;
#pragma unroll
        for (int k = 0; k < S_; k++) fs += svc[p][k];
        llacc += (double)__logf(fs);
        if (j == 0) g_llpart[b * NSEG + s] = llacc;
    } else {
        // ---------------- backward segment ----------------
        float* bb = g_beta + (size_t)b * T_ * S_;
        float en[4];
        int p = 0;
        if (s == 0) {
            // owns [T-256, T); exact init at t = T-1
            bb[(size_t)(T_ - 1) * S_ + j] = 1.f;
            svc[0][j] = eb[(size_t)(T_ - 1) * S_ + j] + EPSV;
#pragma unroll
            for (int i = 0; i < 4; i++)
                en[i] = eb[(size_t)(T_ - 2 - i) * S_ + j] + EPSV;
            NBAR();
            for (int g = 0; g < 63; g++) {
                int t0 = T_ - 2 - 4 * g;
                BSTEP_F(t0, 0)
                BSTEP_F(t0 - 1, 1)
                BSTEP_F(t0 - 2, 2)
                BSTEP_N(t0 - 3, 3)
            }
            BSTEP_F(T_ - LSEG + 2, 0)
            BSTEP_F(T_ - LSEG + 1, 1)
            BSTEP_F(T_ - LSEG, 2)
        } else {
            int thi = T_ - s * LSEG;  // owns [thi-256, thi)
            // warm-up init: beta = 1 at t = thi+32
            svc[0][j] = eb[(size_t)(thi + WSEG) * S_ + j] + EPSV;
#pragma unroll
            for (int i = 0; i < 4; i++)
                en[i] = eb[(size_t)(thi + WSEG - 1 - i) * S_ + j] + EPSV;
            NBAR();
            // warm-up: t = thi+31 .. thi (8 groups)
            for (int g = 0; g < WSEG / 4; g++) {
                int t0 = thi + WSEG - 1 - 4 * g;
                BSTEP_WF(t0, 0)
                BSTEP_WF(t0 - 1, 1)
                BSTEP_WF(t0 - 2, 2)
                BSTEP_WN(t0 - 3, 3)
            }
            // owned: t = thi-1 .. thi-256 (64 groups)
            for (int g = 0; g < 64; g++) {
                int t0 = thi - 1 - 4 * g;
                BSTEP_F(t0, 0)
                BSTEP_F(t0 - 1, 1)
                BSTEP_F(t0 - 2, 2)
                BSTEP_N(t0 - 3, 3)
            }
        }
    }
}

// ---------------- LL reduce: fixed-order, deterministic ----------------
__global__ void llreduce_kernel(float* __restrict__ out_ll) {
    int b = threadIdx.x;  // 0..31
    double s = 0.0;
#pragma unroll
    for (int k = 0; k < NSEG; k++) s += g_llpart[b * NSEG + k];
    out_ll[b] = (float)s;
}

// ---------------- gamma + marginals (unchanged) ----------------
__global__ void __launch_bounds__(256) gamma_kernel(float* __restrict__ out_probs) {
    int b = blockIdx.x >> 4, chunk = blockIdx.x & 15;
    int w = threadIdx.x >> 5, l = threadIdx.x & 31;
    __shared__ float smarg[8][S_];
    const unsigned FULL = 0xffffffffu;
    float mx = 0.f, my = 0.f;
    int tbase = chunk * 256 + w;
    size_t base = (size_t)b * T_ * S_;
#pragma unroll 4
    for (int k = 0; k < 32; k++) {
        int t = tbase + k * 8;
        size_t idx = base + (size_t)t * S_ + 2 * l;
        float2 va = *(const float2*)&g_alpha[idx];
        float2 vb = *(const float2*)&g_beta[idx];
        float px = va.x * vb.x, py = va.y * vb.y;
        float s = px + py;
#pragma unroll
        for (int off = 16; off; off >>= 1) s += __shfl_xor_sync(FULL, s, off);
        float inv = __fdividef(1.f, s);
        px *= inv; py *= inv;
        *(float2*)&out_probs[idx] = make_float2(px, py);
        mx += px; my += py;
    }
    smarg[w][2 * l] = mx;
    smarg[w][2 * l + 1] = my;
    __syncthreads();
    if (threadIdx.x < S_) {
        float s = 0.f;
#pragma unroll
        for (int ww = 0; ww < 8; ww++) s += smarg[ww][threadIdx.x];
        g_margpart[(size_t)blockIdx.x * S_ + threadIdx.x] = s;
    }
}

__global__ void margreduce_kernel(float* __restrict__ out_marg) {
    int i = blockIdx.x * blockDim.x + threadIdx.x;
    int b = i >> 6, j = i & 63;
    float s = 0.f;
#pragma unroll
    for (int c = 0; c < 16; c++) s += g_margpart[(size_t)(b * 16 + c) * S_ + j];
    out_marg[i] = s * (1.f / (float)T_);
}

// ---------------- launch ----------------
extern "C" void kernel_launch(void* const* d_in, const int* in_sizes, int n_in,
                              void* d_out, int out_size) {
    const float* obs = (const float*)d_in[0];
    const float* W1 = (const float*)d_in[1];
    const float* b1 = (const float*)d_in[2];
    const float* W2 = (const float*)d_in[3];
    const float* b2 = (const float*)d_in[4];
    const float* W3 = (const float*)d_in[5];
    const float* b3 = (const float*)d_in[6];
    const float* ltm = (const float*)d_in[7];
    const float* lip = (const float*)d_in[8];
    const float* lr = (const float*)d_in[9];
    const float* lp = (const float*)d_in[10];

    float* out = (float*)d_out;
    float* out_probs = out;
    float* out_marg = out + (size_t)B_ * T_ * S_;
    float* out_dur = out_marg + (size_t)B_ * S_;
    float* out_ll = out_dur + S_;

    const int smem_bytes = (D_ * H_ + H_ * H_ + H_ * S_ + H_ + H_ + S_ + 4 * 4096) * 4;
    cudaFuncSetAttribute(mlp_kernel, cudaFuncAttributeMaxDynamicSharedMemorySize, smem_bytes);

    setup_kernel<<<1, 64>>>(ltm, lip, lr, lp, out_dur);
    mlp_kernel<<<1024, 128, smem_bytes>>>(obs, W1, b1, W2, b2, W3, b3);
    probe_kernel<<<1, 32>>>();
    recursion_kernel<<<B_ * NSEG, 128>>>();
    llreduce_kernel<<<1, 32>>>(out_ll);
    gamma_kernel<<<512, 256>>>(out_probs);
    margreduce_kernel<<<8, 256>>>(out_marg);
}